// round 14
// baseline (speedup 1.0000x reference)
#include <cuda_runtime.h>
#include <cuda_bf16.h>

#define N_NODES 100000
#define N_EDGES 1000000
#define DF 64
#define NC 16
#define SCAN_BLOCKS 148
#define SCAN_THREADS 1024

// ---------------- device scratch (no allocations allowed) ----------------
__device__ int      g_degi[N_NODES];             // zero-invariant across calls
__device__ float    g_dinv[N_NODES];
__device__ int      g_off[N_NODES + 1];
__device__ int      g_cur[N_NODES];
__device__ int      g_bsum[SCAN_BLOCKS];
__device__ int2     g_edge[N_EDGES];             // packed (src, bits(dinv[src]))
__device__ float    g_h1[(size_t)N_NODES * DF];  // X @ W1 (fp32)
__device__ float    g_h2[(size_t)N_NODES * NC];  // relu(agg1) @ W2
__device__ int      g_idx64;
__device__ unsigned g_barcnt[2];                 // cumulative grid-barrier tickets

// ---------------- side stream + events (host objects, created once) -------
static cudaStream_t g_s2 = nullptr;
static cudaEvent_t  g_ev_fork = nullptr, g_ev_join = nullptr;
static struct _StreamInit {
    _StreamInit() {
        cudaStreamCreateWithFlags(&g_s2, cudaStreamNonBlocking);
        cudaEventCreateWithFlags(&g_ev_fork, cudaEventDisableTiming);
        cudaEventCreateWithFlags(&g_ev_join, cudaEventDisableTiming);
    }
} _stream_init;

// ---------------- cumulative grid barrier (graph-replay safe) -------------
__device__ __forceinline__ void grid_barrier(int i) {
    __syncthreads();
    if (threadIdx.x == 0) {
        __threadfence();
        unsigned tkt = atomicAdd(&g_barcnt[i], 1u) + 1u;
        unsigned target = ((tkt + (SCAN_BLOCKS - 1u)) / SCAN_BLOCKS) * SCAN_BLOCKS;
        volatile unsigned* p = &g_barcnt[i];
        while (*p < target) { }
        __threadfence();
    }
    __syncthreads();
}

// ---------------- packed f32x2 helpers -------------------------------------
__device__ __forceinline__ unsigned long long fma_f32x2(unsigned long long a,
                                                        unsigned long long b,
                                                        unsigned long long c) {
    unsigned long long d;
    asm("fma.rn.f32x2 %0, %1, %2, %3;" : "=l"(d) : "l"(a), "l"(b), "l"(c));
    return d;
}
__device__ __forceinline__ unsigned long long dup_f32x2(float v) {
    unsigned long long d;
    asm("mov.b64 %0, {%1, %1};" : "=l"(d) : "f"(v));
    return d;
}

// ---------------- k1: detect index width (1 block) -------------------------
__global__ void detect_kernel(const int* __restrict__ e32) {
    __shared__ int any_nz;
    if (threadIdx.x == 0) any_nz = 0;
    __syncthreads();
    int nz = 0;
    for (int j = threadIdx.x; j < 4096; j += blockDim.x)
        if (e32[2 * j + 1] != 0) nz = 1;
    if (nz) any_nz = 1;
    __syncthreads();
    if (threadIdx.x == 0) g_idx64 = (any_nz == 0) ? 1 : 0;
}

// ---------------- k2: in-degree histogram (full grid) ----------------------
__global__ void degree_kernel(const void* __restrict__ edges) {
    int e = blockIdx.x * blockDim.x + threadIdx.x;
    if (e >= N_EDGES) return;
    const int* e32 = (const int*)edges;
    // low 32-bit word only (valid for both int32 and LE int64 storage)
    int d = g_idx64 ? e32[2 * (N_EDGES + e)] : e32[N_EDGES + e];
    atomicAdd(&g_degi[d], 1);
}

// ---------------- k3: dinv + prefix scan; re-zeroes g_degi -----------------
__global__ __launch_bounds__(SCAN_THREADS)
void scan_kernel() {
    __shared__ int wsum[33];
    int tid = blockIdx.x * SCAN_THREADS + threadIdx.x;
    int v = 0;
    if (tid < N_NODES) {
        v = g_degi[tid];
        g_degi[tid] = 0;                         // maintain zero-invariant
        g_dinv[tid] = rsqrtf((float)v + 1.0f);
    }
    int lane = threadIdx.x & 31, w = threadIdx.x >> 5;
    int x = v;
#pragma unroll
    for (int off = 1; off < 32; off <<= 1) {
        int y = __shfl_up_sync(0xffffffffu, x, off);
        if (lane >= off) x += y;
    }
    if (lane == 31) wsum[w] = x;
    __syncthreads();
    if (w == 0) {
        int y = wsum[lane];
#pragma unroll
        for (int off = 1; off < 32; off <<= 1) {
            int z = __shfl_up_sync(0xffffffffu, y, off);
            if (lane >= off) y += z;
        }
        wsum[lane] = y;
    }
    __syncthreads();
    int incl_local = x + ((w > 0) ? wsum[w - 1] : 0);
    if (threadIdx.x == SCAN_THREADS - 1) g_bsum[blockIdx.x] = incl_local;
    grid_barrier(0);

    if (threadIdx.x < 32) {
        int acc = 0;
        for (int j = threadIdx.x; j < blockIdx.x; j += 32) acc += g_bsum[j];
#pragma unroll
        for (int off = 16; off > 0; off >>= 1)
            acc += __shfl_xor_sync(0xffffffffu, acc, off);
        if (threadIdx.x == 0) wsum[32] = acc;
    }
    __syncthreads();
    int incl = incl_local + wsum[32];
    if (tid < N_NODES) {
        g_off[tid] = incl - v;
        g_cur[tid] = incl - v;
        if (tid == N_NODES - 1) g_off[N_NODES] = incl;
    }
}

// ---------------- k4: CSR build (full grid, counting-sort scatter) ---------
__global__ void build_csr_kernel(const void* __restrict__ edges) {
    int e = blockIdx.x * blockDim.x + threadIdx.x;
    if (e >= N_EDGES) return;
    const int* e32 = (const int*)edges;
    int s, d;
    if (g_idx64) {
        s = e32[2 * e];
        d = e32[2 * (N_EDGES + e)];
    } else {
        s = e32[e];
        d = e32[N_EDGES + e];
    }
    int pos = atomicAdd(&g_cur[d], 1);
    g_edge[pos] = make_int2(s, __float_as_int(g_dinv[s]));
}

// ------- GEMM1: h1 = X @ W1 (64 nodes/block, f32x2, 33KB smem) ------------
__global__ __launch_bounds__(256) void gemm1_kernel(const float* __restrict__ X,
                                                    const float* __restrict__ W1) {
    __shared__ float  xs[64][65];
    __shared__ float2 wst[32][65];
    int tid = threadIdx.x;
    int base = blockIdx.x * 64;
    for (int i = tid; i < 64 * 32; i += 256) {
        int k = i >> 5, p = i & 31;
        wst[p][k] = ((const float2*)W1)[i];      // (W1[k][2p], W1[k][2p+1])
    }
    for (int i = tid; i < 64 * 64; i += 256) {
        int n = i >> 6, k = i & 63;
        int node = base + n;
        xs[n][k] = (node < N_NODES) ? X[(size_t)node * 64 + k] : 0.0f;
    }
    __syncthreads();

    int node_t = tid >> 4;   // 0..15 -> 4 nodes each
    int col_t  = tid & 15;   // 0..15 -> col pairs col_t, col_t+16
    unsigned long long acc[4][2] = {};
#pragma unroll 8
    for (int k = 0; k < 64; k++) {
        unsigned long long wv0 = *(const unsigned long long*)&wst[col_t][k];
        unsigned long long wv1 = *(const unsigned long long*)&wst[col_t + 16][k];
#pragma unroll
        for (int i = 0; i < 4; i++) {
            unsigned long long xv = dup_f32x2(xs[node_t * 4 + i][k]);
            acc[i][0] = fma_f32x2(xv, wv0, acc[i][0]);
            acc[i][1] = fma_f32x2(xv, wv1, acc[i][1]);
        }
    }
#pragma unroll
    for (int i = 0; i < 4; i++) {
        int node = base + node_t * 4 + i;
        if (node < N_NODES) {
            float2* out = (float2*)(g_h1 + (size_t)node * 64);
            out[col_t]      = *(const float2*)&acc[i][0];
            out[col_t + 16] = *(const float2*)&acc[i][1];
        }
    }
}

// ------- agg1 + gemm2 fused: 2 nodes/warp, float4 lanes, smem staging -----
__global__ __launch_bounds__(256) void agg1_gemm2_kernel(const float* __restrict__ b1,
                                                         const float* __restrict__ W2) {
    __shared__ float w2s[64][17];    // [k][c], padded
    __shared__ float x1s[16][65];    // per-node x1 row, padded
    __shared__ int2  est[8][2][16];  // per warp-half edge staging
    int tid = threadIdx.x;
    for (int i = tid; i < 64 * 16; i += 256) w2s[i >> 4][i & 15] = W2[i];
    __syncthreads();

    int wy   = tid >> 5;             // warp 0..7
    int lane = tid & 31;
    int half = lane >> 4;            // 0/1 -> own node
    int c    = lane & 15;            // 0..15 -> cols 4c..4c+3
    unsigned hmask = half ? 0xFFFF0000u : 0x0000FFFFu;
    int node = blockIdx.x * 16 + wy * 2 + half;
    bool active = (node < N_NODES);

    const float4* h1 = (const float4*)g_h1;
    float di = 0.0f;
    float4 acc = make_float4(0.f, 0.f, 0.f, 0.f);
    int beg = 0, end = 0;
    if (active) {
        di = g_dinv[node];
        acc = h1[(size_t)node * 16 + c];
        acc.x *= di; acc.y *= di; acc.z *= di; acc.w *= di;   // self loop
        beg = g_off[node]; end = g_off[node + 1];
    }

    for (int bb = beg; bb < end; bb += 16) {
        if (bb + c < end) est[wy][half][c] = g_edge[bb + c];
        __syncwarp(hmask);
        int cnt = min(end - bb, 16);
        for (int j = 0; j < cnt; j++) {
            int2 e = est[wy][half][j];           // LDS.64 broadcast
            float w = __int_as_float(e.y);
            float4 v = h1[(size_t)e.x * 16 + c]; // LDG.128
            acc.x = fmaf(v.x, w, acc.x);
            acc.y = fmaf(v.y, w, acc.y);
            acc.z = fmaf(v.z, w, acc.z);
            acc.w = fmaf(v.w, w, acc.w);
        }
        __syncwarp(hmask);
    }

    int nidx = wy * 2 + half;
    if (active) {
        float4 bb4 = ((const float4*)b1)[c];
        x1s[nidx][4 * c]     = fmaxf(fmaf(acc.x, di, bb4.x), 0.0f);
        x1s[nidx][4 * c + 1] = fmaxf(fmaf(acc.y, di, bb4.y), 0.0f);
        x1s[nidx][4 * c + 2] = fmaxf(fmaf(acc.z, di, bb4.z), 0.0f);
        x1s[nidx][4 * c + 3] = fmaxf(fmaf(acc.w, di, bb4.w), 0.0f);
    }
    __syncwarp(hmask);

    if (active) {
        float s = 0.0f;
#pragma unroll 8
        for (int k = 0; k < 64; k++)
            s = fmaf(x1s[nidx][k], w2s[k][c], s);
        g_h2[(size_t)node * 16 + c] = s;
    }
}

// ------- agg2: out = A_hat h2 + b2 (2 nodes/warp, smem staging) -----------
__global__ __launch_bounds__(256) void agg2_kernel(const float* __restrict__ b2,
                                                   float* __restrict__ dout) {
    __shared__ int2 est[8][2][16];
    int tid  = threadIdx.x;
    int wy   = tid >> 5;
    int lane = tid & 31;
    int half = lane >> 4;
    int c    = lane & 15;
    unsigned hmask = half ? 0xFFFF0000u : 0x0000FFFFu;
    int node = blockIdx.x * 16 + wy * 2 + half;
    if (node >= N_NODES) return;

    float di = g_dinv[node];
    float acc = g_h2[(size_t)node * 16 + c] * di;
    int beg = g_off[node], end = g_off[node + 1];

    for (int bb = beg; bb < end; bb += 16) {
        if (bb + c < end) est[wy][half][c] = g_edge[bb + c];
        __syncwarp(hmask);
        int cnt = min(end - bb, 16);
        for (int j = 0; j < cnt; j++) {
            int2 e = est[wy][half][j];           // LDS.64 broadcast
            float w = __int_as_float(e.y);
            acc = fmaf(__ldg(&g_h2[(size_t)e.x * 16 + c]), w, acc);
        }
        __syncwarp(hmask);
    }
    dout[(size_t)node * 16 + c] = fmaf(acc, di, b2[c]);
}

// ---------------- launch --------------------------------------------------
extern "C" void kernel_launch(void* const* d_in, const int* in_sizes, int n_in,
                              void* d_out, int out_size) {
    const float* X  = (const float*)d_in[0];
    const void*  EI = (const void*)d_in[1];
    const float* W1 = (const float*)d_in[2];
    const float* b1 = (const float*)d_in[3];
    const float* W2 = (const float*)d_in[4];
    const float* b2 = (const float*)d_in[5];
    float* dout = (float*)d_out;
    (void)in_sizes; (void)n_in; (void)out_size;

    const int T = 256;
    bool fork = (g_s2 != nullptr && g_ev_fork != nullptr && g_ev_join != nullptr);

    if (fork) {
        cudaEventRecord(g_ev_fork, 0);
        cudaStreamWaitEvent(g_s2, g_ev_fork, 0);
        gemm1_kernel<<<(N_NODES + 63) / 64, 256, 0, g_s2>>>(X, W1);
        cudaEventRecord(g_ev_join, g_s2);
    }

    detect_kernel<<<1, 1024>>>((const int*)EI);
    degree_kernel<<<(N_EDGES + T - 1) / T, T>>>(EI);
    scan_kernel<<<SCAN_BLOCKS, SCAN_THREADS>>>();
    build_csr_kernel<<<(N_EDGES + T - 1) / T, T>>>(EI);

    if (fork) {
        cudaStreamWaitEvent(0, g_ev_join, 0);
    } else {
        gemm1_kernel<<<(N_NODES + 63) / 64, 256>>>(X, W1);
    }

    agg1_gemm2_kernel<<<(N_NODES + 15) / 16, 256>>>(b1, W2);
    agg2_kernel<<<(N_NODES + 15) / 16, 256>>>(b2, dout);
}

// round 15
// speedup vs baseline: 1.0695x; 1.0695x over previous
#include <cuda_runtime.h>
#include <cuda_bf16.h>

#define N_NODES 100000
#define N_EDGES 1000000
#define DF 64
#define NC 16
#define CAP 32                       // slots per node; P(deg>32 | Poisson(10)) ~ 2e-9
#define OVF_CAP 32768

// ---------------- device scratch (no allocations allowed) ----------------
__device__ int   g_degi[N_NODES];                // true in-degree (counter)
__device__ int   g_slot[(size_t)N_NODES * CAP];  // first CAP sources per node
__device__ int2  g_ovf[OVF_CAP];                 // overflow edges (dst, src)
__device__ int   g_ovf_cnt;
__device__ float g_h1[(size_t)N_NODES * DF];     // X @ W1 (fp32)
__device__ float g_h2[(size_t)N_NODES * NC];     // relu(agg1) @ W2
__device__ int   g_idx64;

// ---------------- side stream + events (host objects, created once) -------
static cudaStream_t g_s2 = nullptr;
static cudaEvent_t  g_ev_fork = nullptr, g_ev_join = nullptr;
static struct _StreamInit {
    _StreamInit() {
        cudaStreamCreateWithFlags(&g_s2, cudaStreamNonBlocking);
        cudaEventCreateWithFlags(&g_ev_fork, cudaEventDisableTiming);
        cudaEventCreateWithFlags(&g_ev_join, cudaEventDisableTiming);
    }
} _stream_init;

// ---------------- packed f32x2 helpers -------------------------------------
__device__ __forceinline__ unsigned long long fma_f32x2(unsigned long long a,
                                                        unsigned long long b,
                                                        unsigned long long c) {
    unsigned long long d;
    asm("fma.rn.f32x2 %0, %1, %2, %3;" : "=l"(d) : "l"(a), "l"(b), "l"(c));
    return d;
}
__device__ __forceinline__ unsigned long long dup_f32x2(float v) {
    unsigned long long d;
    asm("mov.b64 %0, {%1, %1};" : "=l"(d) : "f"(v));
    return d;
}

// ---------------- k1: zero counters + detect index width -------------------
__global__ void zero_detect_kernel(const int* __restrict__ e32) {
    int i = blockIdx.x * blockDim.x + threadIdx.x;
    if (i < N_NODES) g_degi[i] = 0;
    if (blockIdx.x == 0) {
        __shared__ int any_nz;
        if (threadIdx.x == 0) { any_nz = 0; g_ovf_cnt = 0; }
        __syncthreads();
        int nz = 0;
        for (int j = threadIdx.x; j < 4096; j += blockDim.x)
            if (e32[2 * j + 1] != 0) nz = 1;
        if (nz) any_nz = 1;
        __syncthreads();
        if (threadIdx.x == 0) g_idx64 = (any_nz == 0) ? 1 : 0;
    }
}

// ---------------- k2: one-pass slot scatter (count + adjacency) ------------
__global__ void slot_scatter_kernel(const void* __restrict__ edges) {
    int e = blockIdx.x * blockDim.x + threadIdx.x;
    if (e >= N_EDGES) return;
    const int* e32 = (const int*)edges;
    int s, d;
    if (g_idx64) {                    // low 32-bit word only (LE int64)
        s = e32[2 * e];
        d = e32[2 * (N_EDGES + e)];
    } else {
        s = e32[e];
        d = e32[N_EDGES + e];
    }
    int pos = atomicAdd(&g_degi[d], 1);
    if (pos < CAP) {
        g_slot[(size_t)d * CAP + pos] = s;
    } else {
        int o = atomicAdd(&g_ovf_cnt, 1);
        if (o < OVF_CAP) g_ovf[o] = make_int2(d, s);
    }
}

// ------- GEMM1: h1 = X @ W1 (64 nodes/block, f32x2, 33KB smem) ------------
__global__ __launch_bounds__(256) void gemm1_kernel(const float* __restrict__ X,
                                                    const float* __restrict__ W1) {
    __shared__ float  xs[64][65];
    __shared__ float2 wst[32][65];
    int tid = threadIdx.x;
    int base = blockIdx.x * 64;
    for (int i = tid; i < 64 * 32; i += 256) {
        int k = i >> 5, p = i & 31;
        wst[p][k] = ((const float2*)W1)[i];      // (W1[k][2p], W1[k][2p+1])
    }
    for (int i = tid; i < 64 * 64; i += 256) {
        int n = i >> 6, k = i & 63;
        int node = base + n;
        xs[n][k] = (node < N_NODES) ? X[(size_t)node * 64 + k] : 0.0f;
    }
    __syncthreads();

    int node_t = tid >> 4;   // 0..15 -> 4 nodes each
    int col_t  = tid & 15;   // 0..15 -> col pairs col_t, col_t+16
    unsigned long long acc[4][2] = {};
#pragma unroll 8
    for (int k = 0; k < 64; k++) {
        unsigned long long wv0 = *(const unsigned long long*)&wst[col_t][k];
        unsigned long long wv1 = *(const unsigned long long*)&wst[col_t + 16][k];
#pragma unroll
        for (int i = 0; i < 4; i++) {
            unsigned long long xv = dup_f32x2(xs[node_t * 4 + i][k]);
            acc[i][0] = fma_f32x2(xv, wv0, acc[i][0]);
            acc[i][1] = fma_f32x2(xv, wv1, acc[i][1]);
        }
    }
#pragma unroll
    for (int i = 0; i < 4; i++) {
        int node = base + node_t * 4 + i;
        if (node < N_NODES) {
            float2* out = (float2*)(g_h1 + (size_t)node * 64);
            out[col_t]      = *(const float2*)&acc[i][0];
            out[col_t + 16] = *(const float2*)&acc[i][1];
        }
    }
}

// ------- agg1 + gemm2 fused: 2 nodes/warp, slot traversal ------------------
__global__ __launch_bounds__(256) void agg1_gemm2_kernel(const float* __restrict__ b1,
                                                         const float* __restrict__ W2) {
    __shared__ float w2s[64][17];    // [k][c], padded
    __shared__ float x1s[16][65];    // per-node x1 row, padded
    __shared__ int2  est[8][2][16];  // per warp-half (src, bits(dinv[src]))
    int tid = threadIdx.x;
    for (int i = tid; i < 64 * 16; i += 256) w2s[i >> 4][i & 15] = W2[i];
    __syncthreads();

    int wy   = tid >> 5;             // warp 0..7
    int lane = tid & 31;
    int half = lane >> 4;            // 0/1 -> own node
    int c    = lane & 15;            // 0..15 -> cols 4c..4c+3
    unsigned hmask = half ? 0xFFFF0000u : 0x0000FFFFu;
    int node = blockIdx.x * 16 + wy * 2 + half;
    bool active = (node < N_NODES);

    const float4* h1 = (const float4*)g_h1;
    float di = 0.0f;
    float4 acc = make_float4(0.f, 0.f, 0.f, 0.f);
    int cnt = 0, cnt32 = 0;
    if (active) {
        cnt = g_degi[node];
        cnt32 = min(cnt, CAP);
        di = rsqrtf((float)cnt + 1.0f);
        acc = h1[(size_t)node * 16 + c];
        acc.x *= di; acc.y *= di; acc.z *= di; acc.w *= di;   // self loop
    }
    const int* slotp = g_slot + (size_t)node * CAP;

    for (int bb = 0; bb < cnt32; bb += 16) {
        if (bb + c < cnt32) {
            int s = slotp[bb + c];
            float w = rsqrtf((float)__ldg(&g_degi[s]) + 1.0f);
            est[wy][half][c] = make_int2(s, __float_as_int(w));
        }
        __syncwarp(hmask);
        int m = min(cnt32 - bb, 16);
        for (int j = 0; j < m; j++) {
            int2 e = est[wy][half][j];           // LDS.64 broadcast
            float w = __int_as_float(e.y);
            float4 v = h1[(size_t)e.x * 16 + c]; // LDG.128
            acc.x = fmaf(v.x, w, acc.x);
            acc.y = fmaf(v.y, w, acc.y);
            acc.z = fmaf(v.z, w, acc.z);
            acc.w = fmaf(v.w, w, acc.w);
        }
        __syncwarp(hmask);
    }
    if (cnt > CAP) {                              // overflow (expected: never)
        int no = min(g_ovf_cnt, OVF_CAP);
        for (int o = 0; o < no; o++) {
            int2 ev = g_ovf[o];
            if (ev.x == node) {
                float w = rsqrtf((float)__ldg(&g_degi[ev.y]) + 1.0f);
                float4 v = h1[(size_t)ev.y * 16 + c];
                acc.x = fmaf(v.x, w, acc.x);
                acc.y = fmaf(v.y, w, acc.y);
                acc.z = fmaf(v.z, w, acc.z);
                acc.w = fmaf(v.w, w, acc.w);
            }
        }
    }

    int nidx = wy * 2 + half;
    if (active) {
        float4 bb4 = ((const float4*)b1)[c];
        x1s[nidx][4 * c]     = fmaxf(fmaf(acc.x, di, bb4.x), 0.0f);
        x1s[nidx][4 * c + 1] = fmaxf(fmaf(acc.y, di, bb4.y), 0.0f);
        x1s[nidx][4 * c + 2] = fmaxf(fmaf(acc.z, di, bb4.z), 0.0f);
        x1s[nidx][4 * c + 3] = fmaxf(fmaf(acc.w, di, bb4.w), 0.0f);
    }
    __syncwarp(hmask);

    if (active) {
        float s = 0.0f;
#pragma unroll 8
        for (int k = 0; k < 64; k++)
            s = fmaf(x1s[nidx][k], w2s[k][c], s);
        g_h2[(size_t)node * 16 + c] = s;
    }
}

// ------- agg2: out = A_hat h2 + b2 (2 nodes/warp, slot traversal) ----------
__global__ __launch_bounds__(256) void agg2_kernel(const float* __restrict__ b2,
                                                   float* __restrict__ dout) {
    __shared__ int2 est[8][2][16];
    int tid  = threadIdx.x;
    int wy   = tid >> 5;
    int lane = tid & 31;
    int half = lane >> 4;
    int c    = lane & 15;
    unsigned hmask = half ? 0xFFFF0000u : 0x0000FFFFu;
    int node = blockIdx.x * 16 + wy * 2 + half;
    if (node >= N_NODES) return;

    int cnt = g_degi[node];
    int cnt32 = min(cnt, CAP);
    float di = rsqrtf((float)cnt + 1.0f);
    float acc = g_h2[(size_t)node * 16 + c] * di;
    const int* slotp = g_slot + (size_t)node * CAP;

    for (int bb = 0; bb < cnt32; bb += 16) {
        if (bb + c < cnt32) {
            int s = slotp[bb + c];
            float w = rsqrtf((float)__ldg(&g_degi[s]) + 1.0f);
            est[wy][half][c] = make_int2(s, __float_as_int(w));
        }
        __syncwarp(hmask);
        int m = min(cnt32 - bb, 16);
        for (int j = 0; j < m; j++) {
            int2 e = est[wy][half][j];           // LDS.64 broadcast
            float w = __int_as_float(e.y);
            acc = fmaf(__ldg(&g_h2[(size_t)e.x * 16 + c]), w, acc);
        }
        __syncwarp(hmask);
    }
    if (cnt > CAP) {                              // overflow (expected: never)
        int no = min(g_ovf_cnt, OVF_CAP);
        for (int o = 0; o < no; o++) {
            int2 ev = g_ovf[o];
            if (ev.x == node) {
                float w = rsqrtf((float)__ldg(&g_degi[ev.y]) + 1.0f);
                acc = fmaf(__ldg(&g_h2[(size_t)ev.y * 16 + c]), w, acc);
            }
        }
    }
    dout[(size_t)node * 16 + c] = fmaf(acc, di, b2[c]);
}

// ---------------- launch --------------------------------------------------
extern "C" void kernel_launch(void* const* d_in, const int* in_sizes, int n_in,
                              void* d_out, int out_size) {
    const float* X  = (const float*)d_in[0];
    const void*  EI = (const void*)d_in[1];
    const float* W1 = (const float*)d_in[2];
    const float* b1 = (const float*)d_in[3];
    const float* W2 = (const float*)d_in[4];
    const float* b2 = (const float*)d_in[5];
    float* dout = (float*)d_out;
    (void)in_sizes; (void)n_in; (void)out_size;

    const int T = 256;
    bool fork = (g_s2 != nullptr && g_ev_fork != nullptr && g_ev_join != nullptr);

    if (fork) {
        cudaEventRecord(g_ev_fork, 0);
        cudaStreamWaitEvent(g_s2, g_ev_fork, 0);
        gemm1_kernel<<<(N_NODES + 63) / 64, 256, 0, g_s2>>>(X, W1);
        cudaEventRecord(g_ev_join, g_s2);
    }

    zero_detect_kernel<<<(N_NODES + T - 1) / T, T>>>((const int*)EI);
    slot_scatter_kernel<<<(N_EDGES + T - 1) / T, T>>>(EI);

    if (fork) {
        cudaStreamWaitEvent(0, g_ev_join, 0);
    } else {
        gemm1_kernel<<<(N_NODES + 63) / 64, 256>>>(X, W1);
    }

    agg1_gemm2_kernel<<<(N_NODES + 15) / 16, 256>>>(b1, W2);
    agg2_kernel<<<(N_NODES + 15) / 16, 256>>>(b2, dout);
}

// round 16
// speedup vs baseline: 1.0718x; 1.0022x over previous
#include <cuda_runtime.h>
#include <cuda_bf16.h>

#define N_NODES 100000
#define N_EDGES 1000000
#define DF 64
#define NC 16
#define CAP 32                       // slots per node; P(deg>32 | Poisson(10)) ~ 2e-9
#define OVF_CAP 32768

// ---------------- device scratch (no allocations allowed) ----------------
__device__ int   g_degi[N_NODES];                // true in-degree (counter)
__device__ int   g_slot[(size_t)N_NODES * CAP];  // first CAP sources per node
__device__ int2  g_ovf[OVF_CAP];                 // overflow edges (dst, src)
__device__ int   g_ovf_cnt;
__device__ float g_h1[(size_t)N_NODES * DF];     // X @ W1 (fp32)
__device__ float g_h2[(size_t)N_NODES * NC];     // relu(agg1) @ W2
__device__ int   g_idx64;

// ---------------- side stream + events (host objects, created once) -------
static cudaStream_t g_s2 = nullptr;
static cudaEvent_t  g_ev_fork = nullptr, g_ev_join = nullptr;
static struct _StreamInit {
    _StreamInit() {
        cudaStreamCreateWithFlags(&g_s2, cudaStreamNonBlocking);
        cudaEventCreateWithFlags(&g_ev_fork, cudaEventDisableTiming);
        cudaEventCreateWithFlags(&g_ev_join, cudaEventDisableTiming);
    }
} _stream_init;

// ---------------- packed f32x2 helpers -------------------------------------
__device__ __forceinline__ unsigned long long fma_f32x2(unsigned long long a,
                                                        unsigned long long b,
                                                        unsigned long long c) {
    unsigned long long d;
    asm("fma.rn.f32x2 %0, %1, %2, %3;" : "=l"(d) : "l"(a), "l"(b), "l"(c));
    return d;
}
__device__ __forceinline__ unsigned long long dup_f32x2(float v) {
    unsigned long long d;
    asm("mov.b64 %0, {%1, %1};" : "=l"(d) : "f"(v));
    return d;
}

// row pointers via 32-bit byte offsets (buffers < 4GB)
__device__ __forceinline__ const float4* h1_row(const float4* base, int src, int c) {
    return (const float4*)((const char*)base + (((unsigned)src) << 8)) + c;
}
__device__ __forceinline__ const float* h2_row(const float* base, int src, int c) {
    return (const float*)((const char*)base + (((unsigned)src) << 6)) + c;
}

// ---------------- k1: zero counters + detect index width -------------------
__global__ void zero_detect_kernel(const int* __restrict__ e32) {
    int i = blockIdx.x * blockDim.x + threadIdx.x;
    if (i < N_NODES) g_degi[i] = 0;
    if (blockIdx.x == 0) {
        __shared__ int any_nz;
        if (threadIdx.x == 0) { any_nz = 0; g_ovf_cnt = 0; }
        __syncthreads();
        int nz = 0;
        for (int j = threadIdx.x; j < 4096; j += blockDim.x)
            if (e32[2 * j + 1] != 0) nz = 1;
        if (nz) any_nz = 1;
        __syncthreads();
        if (threadIdx.x == 0) g_idx64 = (any_nz == 0) ? 1 : 0;
    }
}

// ---------------- k2: one-pass slot scatter (count + adjacency) ------------
__global__ void slot_scatter_kernel(const void* __restrict__ edges) {
    int e = blockIdx.x * blockDim.x + threadIdx.x;
    if (e >= N_EDGES) return;
    const int* e32 = (const int*)edges;
    int s, d;
    if (g_idx64) {                    // low 32-bit word only (LE int64)
        s = e32[2 * e];
        d = e32[2 * (N_EDGES + e)];
    } else {
        s = e32[e];
        d = e32[N_EDGES + e];
    }
    int pos = atomicAdd(&g_degi[d], 1);
    if (pos < CAP) {
        g_slot[(size_t)d * CAP + pos] = s;
    } else {
        int o = atomicAdd(&g_ovf_cnt, 1);
        if (o < OVF_CAP) g_ovf[o] = make_int2(d, s);
    }
}

// ------- GEMM1: h1 = X @ W1 (64 nodes/block, f32x2, 33KB smem) ------------
__global__ __launch_bounds__(256) void gemm1_kernel(const float* __restrict__ X,
                                                    const float* __restrict__ W1) {
    __shared__ float  xs[64][65];
    __shared__ float2 wst[32][65];
    int tid = threadIdx.x;
    int base = blockIdx.x * 64;
    for (int i = tid; i < 64 * 32; i += 256) {
        int k = i >> 5, p = i & 31;
        wst[p][k] = ((const float2*)W1)[i];      // (W1[k][2p], W1[k][2p+1])
    }
    for (int i = tid; i < 64 * 64; i += 256) {
        int n = i >> 6, k = i & 63;
        int node = base + n;
        xs[n][k] = (node < N_NODES) ? X[(size_t)node * 64 + k] : 0.0f;
    }
    __syncthreads();

    int node_t = tid >> 4;   // 0..15 -> 4 nodes each
    int col_t  = tid & 15;   // 0..15 -> col pairs col_t, col_t+16
    unsigned long long acc[4][2] = {};
#pragma unroll 8
    for (int k = 0; k < 64; k++) {
        unsigned long long wv0 = *(const unsigned long long*)&wst[col_t][k];
        unsigned long long wv1 = *(const unsigned long long*)&wst[col_t + 16][k];
#pragma unroll
        for (int i = 0; i < 4; i++) {
            unsigned long long xv = dup_f32x2(xs[node_t * 4 + i][k]);
            acc[i][0] = fma_f32x2(xv, wv0, acc[i][0]);
            acc[i][1] = fma_f32x2(xv, wv1, acc[i][1]);
        }
    }
#pragma unroll
    for (int i = 0; i < 4; i++) {
        int node = base + node_t * 4 + i;
        if (node < N_NODES) {
            float2* out = (float2*)(g_h1 + (size_t)node * 64);
            out[col_t]      = *(const float2*)&acc[i][0];
            out[col_t + 16] = *(const float2*)&acc[i][1];
        }
    }
}

// ------- agg1 + gemm2 fused: 2 nodes/warp, 4-edge unrolled gather ----------
__global__ __launch_bounds__(256) void agg1_gemm2_kernel(const float* __restrict__ b1,
                                                         const float* __restrict__ W2) {
    __shared__ float w2s[64][17];    // [k][c], padded
    __shared__ float x1s[16][65];    // per-node x1 row, padded
    __shared__ int2  est[8][2][16];  // per warp-half (src, bits(dinv[src]))
    int tid = threadIdx.x;
    for (int i = tid; i < 64 * 16; i += 256) w2s[i >> 4][i & 15] = W2[i];
    __syncthreads();

    int wy   = tid >> 5;             // warp 0..7
    int lane = tid & 31;
    int half = lane >> 4;            // 0/1 -> own node
    int c    = lane & 15;            // 0..15 -> cols 4c..4c+3
    unsigned hmask = half ? 0xFFFF0000u : 0x0000FFFFu;
    int node = blockIdx.x * 16 + wy * 2 + half;
    bool active = (node < N_NODES);

    const float4* h1 = (const float4*)g_h1;
    float di = 0.0f;
    float4 acc = make_float4(0.f, 0.f, 0.f, 0.f);
    int cnt = 0, cnt32 = 0;
    if (active) {
        cnt = g_degi[node];
        cnt32 = min(cnt, CAP);
        di = rsqrtf((float)cnt + 1.0f);
        acc = *h1_row(h1, node, c);
        acc.x *= di; acc.y *= di; acc.z *= di; acc.w *= di;   // self loop
    }
    const int* slotp = g_slot + (size_t)node * CAP;

    for (int bb = 0; bb < cnt32; bb += 16) {
        if (bb + c < cnt32) {
            int s = slotp[bb + c];
            float w = rsqrtf((float)__ldg(&g_degi[s]) + 1.0f);
            est[wy][half][c] = make_int2(s, __float_as_int(w));
        }
        __syncwarp(hmask);
        int m = min(cnt32 - bb, 16);
        int j = 0;
        for (; j + 4 <= m; j += 4) {            // MLP-4 unrolled body
            int2 e0 = est[wy][half][j],     e1 = est[wy][half][j + 1];
            int2 e2 = est[wy][half][j + 2], e3 = est[wy][half][j + 3];
            float4 v0 = *h1_row(h1, e0.x, c);
            float4 v1 = *h1_row(h1, e1.x, c);
            float4 v2 = *h1_row(h1, e2.x, c);
            float4 v3 = *h1_row(h1, e3.x, c);
            float w0 = __int_as_float(e0.y), w1 = __int_as_float(e1.y);
            float w2 = __int_as_float(e2.y), w3 = __int_as_float(e3.y);
            acc.x = fmaf(v0.x, w0, acc.x); acc.y = fmaf(v0.y, w0, acc.y);
            acc.z = fmaf(v0.z, w0, acc.z); acc.w = fmaf(v0.w, w0, acc.w);
            acc.x = fmaf(v1.x, w1, acc.x); acc.y = fmaf(v1.y, w1, acc.y);
            acc.z = fmaf(v1.z, w1, acc.z); acc.w = fmaf(v1.w, w1, acc.w);
            acc.x = fmaf(v2.x, w2, acc.x); acc.y = fmaf(v2.y, w2, acc.y);
            acc.z = fmaf(v2.z, w2, acc.z); acc.w = fmaf(v2.w, w2, acc.w);
            acc.x = fmaf(v3.x, w3, acc.x); acc.y = fmaf(v3.y, w3, acc.y);
            acc.z = fmaf(v3.z, w3, acc.z); acc.w = fmaf(v3.w, w3, acc.w);
        }
        for (; j < m; j++) {
            int2 e = est[wy][half][j];
            float w = __int_as_float(e.y);
            float4 v = *h1_row(h1, e.x, c);
            acc.x = fmaf(v.x, w, acc.x); acc.y = fmaf(v.y, w, acc.y);
            acc.z = fmaf(v.z, w, acc.z); acc.w = fmaf(v.w, w, acc.w);
        }
        __syncwarp(hmask);
    }
    if (cnt > CAP) {                              // overflow (expected: never)
        int no = min(g_ovf_cnt, OVF_CAP);
        for (int o = 0; o < no; o++) {
            int2 ev = g_ovf[o];
            if (ev.x == node) {
                float w = rsqrtf((float)__ldg(&g_degi[ev.y]) + 1.0f);
                float4 v = *h1_row(h1, ev.y, c);
                acc.x = fmaf(v.x, w, acc.x); acc.y = fmaf(v.y, w, acc.y);
                acc.z = fmaf(v.z, w, acc.z); acc.w = fmaf(v.w, w, acc.w);
            }
        }
    }

    int nidx = wy * 2 + half;
    if (active) {
        float4 bb4 = ((const float4*)b1)[c];
        x1s[nidx][4 * c]     = fmaxf(fmaf(acc.x, di, bb4.x), 0.0f);
        x1s[nidx][4 * c + 1] = fmaxf(fmaf(acc.y, di, bb4.y), 0.0f);
        x1s[nidx][4 * c + 2] = fmaxf(fmaf(acc.z, di, bb4.z), 0.0f);
        x1s[nidx][4 * c + 3] = fmaxf(fmaf(acc.w, di, bb4.w), 0.0f);
    }
    __syncwarp(hmask);

    if (active) {
        float s = 0.0f;
#pragma unroll 8
        for (int k = 0; k < 64; k++)
            s = fmaf(x1s[nidx][k], w2s[k][c], s);
        g_h2[(size_t)node * 16 + c] = s;
    }
}

// ------- agg2: out = A_hat h2 + b2 (2 nodes/warp, 4-edge unrolled) ---------
__global__ __launch_bounds__(256) void agg2_kernel(const float* __restrict__ b2,
                                                   float* __restrict__ dout) {
    __shared__ int2 est[8][2][16];
    int tid  = threadIdx.x;
    int wy   = tid >> 5;
    int lane = tid & 31;
    int half = lane >> 4;
    int c    = lane & 15;
    unsigned hmask = half ? 0xFFFF0000u : 0x0000FFFFu;
    int node = blockIdx.x * 16 + wy * 2 + half;
    if (node >= N_NODES) return;

    int cnt = g_degi[node];
    int cnt32 = min(cnt, CAP);
    float di = rsqrtf((float)cnt + 1.0f);
    const float* h2 = g_h2;
    float acc = *h2_row(h2, node, c) * di;
    const int* slotp = g_slot + (size_t)node * CAP;

    for (int bb = 0; bb < cnt32; bb += 16) {
        if (bb + c < cnt32) {
            int s = slotp[bb + c];
            float w = rsqrtf((float)__ldg(&g_degi[s]) + 1.0f);
            est[wy][half][c] = make_int2(s, __float_as_int(w));
        }
        __syncwarp(hmask);
        int m = min(cnt32 - bb, 16);
        int j = 0;
        for (; j + 4 <= m; j += 4) {            // MLP-4 unrolled body
            int2 e0 = est[wy][half][j],     e1 = est[wy][half][j + 1];
            int2 e2 = est[wy][half][j + 2], e3 = est[wy][half][j + 3];
            float v0 = *h2_row(h2, e0.x, c);
            float v1 = *h2_row(h2, e1.x, c);
            float v2 = *h2_row(h2, e2.x, c);
            float v3 = *h2_row(h2, e3.x, c);
            acc = fmaf(v0, __int_as_float(e0.y), acc);
            acc = fmaf(v1, __int_as_float(e1.y), acc);
            acc = fmaf(v2, __int_as_float(e2.y), acc);
            acc = fmaf(v3, __int_as_float(e3.y), acc);
        }
        for (; j < m; j++) {
            int2 e = est[wy][half][j];
            acc = fmaf(*h2_row(h2, e.x, c), __int_as_float(e.y), acc);
        }
        __syncwarp(hmask);
    }
    if (cnt > CAP) {                              // overflow (expected: never)
        int no = min(g_ovf_cnt, OVF_CAP);
        for (int o = 0; o < no; o++) {
            int2 ev = g_ovf[o];
            if (ev.x == node) {
                float w = rsqrtf((float)__ldg(&g_degi[ev.y]) + 1.0f);
                acc = fmaf(*h2_row(h2, ev.y, c), w, acc);
            }
        }
    }
    dout[(size_t)node * 16 + c] = fmaf(acc, di, b2[c]);
}

// ---------------- launch --------------------------------------------------
extern "C" void kernel_launch(void* const* d_in, const int* in_sizes, int n_in,
                              void* d_out, int out_size) {
    const float* X  = (const float*)d_in[0];
    const void*  EI = (const void*)d_in[1];
    const float* W1 = (const float*)d_in[2];
    const float* b1 = (const float*)d_in[3];
    const float* W2 = (const float*)d_in[4];
    const float* b2 = (const float*)d_in[5];
    float* dout = (float*)d_out;
    (void)in_sizes; (void)n_in; (void)out_size;

    const int T = 256;
    bool fork = (g_s2 != nullptr && g_ev_fork != nullptr && g_ev_join != nullptr);

    if (fork) {
        cudaEventRecord(g_ev_fork, 0);
        cudaStreamWaitEvent(g_s2, g_ev_fork, 0);
        gemm1_kernel<<<(N_NODES + 63) / 64, 256, 0, g_s2>>>(X, W1);
        cudaEventRecord(g_ev_join, g_s2);
    }

    zero_detect_kernel<<<(N_NODES + T - 1) / T, T>>>((const int*)EI);
    slot_scatter_kernel<<<(N_EDGES + T - 1) / T, T>>>(EI);

    if (fork) {
        cudaStreamWaitEvent(0, g_ev_join, 0);
    } else {
        gemm1_kernel<<<(N_NODES + 63) / 64, 256>>>(X, W1);
    }

    agg1_gemm2_kernel<<<(N_NODES + 15) / 16, 256>>>(b1, W2);
    agg2_kernel<<<(N_NODES + 15) / 16, 256>>>(b2, dout);
}